// round 2
// baseline (speedup 1.0000x reference)
#include <cuda_runtime.h>
#include <cuda_bf16.h>

// loss = [pen_neg(v) + (N*sum(r^2) - (sum r)^2)] / (N(N-1)/2) + pen_range(v)
// where r_i = haversine(st_i, q) - v * t_i, DEG = 3.14/180 (sic).

#define NBLOCKS 64
#define NTHREADS 128
#define N_TOTAL 8192

// Scratch: per-block partial sums (S1, S2) in double. No device allocs allowed.
__device__ double g_part_s1[NBLOCKS];
__device__ double g_part_s2[NBLOCKS];

__global__ void __launch_bounds__(NTHREADS)
find_loc_partial(const float* __restrict__ lat,
                 const float* __restrict__ lon,
                 const float* __restrict__ v,
                 const float* __restrict__ st_lat,
                 const float* __restrict__ st_lon,
                 const float* __restrict__ times,
                 int n)
{
    const float DEG = 3.14f / 180.0f;
    const float R   = 6373.0f;

    const float la2 = lat[0] * DEG;
    const float lo2 = lon[0] * DEG;
    const float vv  = v[0];
    const float cos_la2 = cosf(la2);

    int i = blockIdx.x * NTHREADS + threadIdx.x;

    double s1 = 0.0, s2 = 0.0;
    if (i < n) {
        float la1 = st_lat[i] * DEG;
        float lo1 = st_lon[i] * DEG;
        float sdla = sinf((la2 - la1) * 0.5f);
        float sdlo = sinf((lo2 - lo1) * 0.5f);
        float a = sdla * sdla + cosf(la1) * cos_la2 * (sdlo * sdlo);
        float c = 2.0f * atan2f(sqrtf(a), sqrtf(1.0f - a));
        float d = R * c;
        float r = d - vv * times[i];
        s1 = (double)r;
        s2 = (double)r * (double)r;
    }

    // warp reduction (doubles via shfl on 64-bit)
    #pragma unroll
    for (int off = 16; off > 0; off >>= 1) {
        s1 += __shfl_down_sync(0xFFFFFFFFu, s1, off);
        s2 += __shfl_down_sync(0xFFFFFFFFu, s2, off);
    }

    __shared__ double sh1[NTHREADS / 32];
    __shared__ double sh2[NTHREADS / 32];
    int lane = threadIdx.x & 31;
    int wid  = threadIdx.x >> 5;
    if (lane == 0) { sh1[wid] = s1; sh2[wid] = s2; }
    __syncthreads();

    if (wid == 0) {
        s1 = (lane < NTHREADS / 32) ? sh1[lane] : 0.0;
        s2 = (lane < NTHREADS / 32) ? sh2[lane] : 0.0;
        #pragma unroll
        for (int off = (NTHREADS / 64); off > 0; off >>= 1) {
            s1 += __shfl_down_sync(0xFFFFFFFFu, s1, off);
            s2 += __shfl_down_sync(0xFFFFFFFFu, s2, off);
        }
        if (lane == 0) {
            g_part_s1[blockIdx.x] = s1;
            g_part_s2[blockIdx.x] = s2;
        }
    }
}

__global__ void __launch_bounds__(64)
find_loc_finalize(const float* __restrict__ v, float* __restrict__ out, int n)
{
    int t = threadIdx.x;  // 64 threads, one partial each
    double s1 = g_part_s1[t];
    double s2 = g_part_s2[t];

    // two-warp reduction via shared
    __shared__ double sh1[2], sh2[2];
    #pragma unroll
    for (int off = 16; off > 0; off >>= 1) {
        s1 += __shfl_down_sync(0xFFFFFFFFu, s1, off);
        s2 += __shfl_down_sync(0xFFFFFFFFu, s2, off);
    }
    int lane = t & 31, wid = t >> 5;
    if (lane == 0) { sh1[wid] = s1; sh2[wid] = s2; }
    __syncthreads();

    if (t == 0) {
        double S1 = sh1[0] + sh1[1];
        double S2 = sh2[0] + sh2[1];
        double dn = (double)n;
        double pair_sum = dn * S2 - S1 * S1;

        float vv = v[0];
        double pen_neg = (vv < 0.0f) ? (double)(-vv * 10.0f) : 0.0;
        double num = dn * (dn - 1.0) * 0.5;
        double loss = (pen_neg + pair_sum) / num;
        float dv = vv - 6.0f;
        if (fabsf(dv) > 4.0f) loss += 10.0 * (double)dv * (double)dv;
        out[0] = (float)loss;
    }
}

extern "C" void kernel_launch(void* const* d_in, const int* in_sizes, int n_in,
                              void* d_out, int out_size)
{
    const float* lat    = (const float*)d_in[0];
    const float* lon    = (const float*)d_in[1];
    const float* v      = (const float*)d_in[2];
    const float* st_lat = (const float*)d_in[3];
    const float* st_lon = (const float*)d_in[4];
    const float* times  = (const float*)d_in[5];
    float* out = (float*)d_out;
    int n = in_sizes[3];  // station count

    find_loc_partial<<<NBLOCKS, NTHREADS>>>(lat, lon, v, st_lat, st_lon, times, n);
    find_loc_finalize<<<1, 64>>>(v, out, n);
}